// round 3
// baseline (speedup 1.0000x reference)
#include <cuda_runtime.h>
#include <math.h>

#define C_    384
#define HH    56
#define WW    56
#define HWSZ  3136
#define NB    16
#define EPSV  1e-5f

// Scratch for x_pw (pointwise+BN+residual result): 16*384*3136 floats = 77 MB
__device__ float g_xpw[(size_t)NB * C_ * HWSZ];

// ---------------------------------------------------------------------------
// Kernel 1: y = einsum('bchw,oc->bohw', x, pw_w); x_pw = bn(y) + x
// Batched SGEMM: per batch, W[384,384] x X[384,3136].
// Block tile 128 (O) x 64 (HW), BK=8, 128 threads, 8x8 per-thread tile.
// Double-buffered smem, one sync per K-step. All dims divide exactly.
// ---------------------------------------------------------------------------
__global__ void __launch_bounds__(128) pw_bn_res_kernel(
    const float* __restrict__ x,   const float* __restrict__ w,
    const float* __restrict__ gg,  const float* __restrict__ bb,
    const float* __restrict__ mm,  const float* __restrict__ vv)
{
    __shared__ float sW[2][8][132];   // [buf][k][o], padded
    __shared__ float sX[2][8][68];    // [buf][k][hw], padded

    const int bi  = blockIdx.z;
    const int o0  = blockIdx.y * 128;
    const int hw0 = blockIdx.x * 64;
    const int tid = threadIdx.x;
    const int tx  = tid & 7;       // hw direction: 8 threads * 8 cols = 64
    const int ty  = tid >> 3;      // o  direction: 16 threads * 8 rows = 128

    float acc[8][8];
#pragma unroll
    for (int i = 0; i < 8; i++)
#pragma unroll
        for (int j = 0; j < 8; j++) acc[i][j] = 0.f;

    const float* xb = x + (size_t)bi * C_ * HWSZ;

    // Loader roles
    const float* wp = w + (size_t)(o0 + tid) * C_;      // one W row per thread
    const int xkk = tid >> 4;                           // 0..7
    const int xj4 = (tid & 15) * 4;                     // 0..60
    const float* xp = xb + (size_t)xkk * HWSZ + hw0 + xj4;

    // Preload k0 = 0 into buffer 0
    {
        float4 w0 = *(const float4*)(wp + 0);
        float4 w1 = *(const float4*)(wp + 4);
        sW[0][0][tid] = w0.x; sW[0][1][tid] = w0.y;
        sW[0][2][tid] = w0.z; sW[0][3][tid] = w0.w;
        sW[0][4][tid] = w1.x; sW[0][5][tid] = w1.y;
        sW[0][6][tid] = w1.z; sW[0][7][tid] = w1.w;
        float4 xv = *(const float4*)(xp);
        *(float4*)(&sX[0][xkk][xj4]) = xv;
    }
    __syncthreads();

    int buf = 0;
    for (int k0 = 0; k0 < C_; k0 += 8) {
        const bool has_next = (k0 + 8) < C_;
        float4 w0n, w1n, xvn;
        if (has_next) {
            w0n = *(const float4*)(wp + k0 + 8);
            w1n = *(const float4*)(wp + k0 + 12);
            xvn = *(const float4*)(xp + (size_t)(k0 + 8) * HWSZ);
        }

#pragma unroll
        for (int kk = 0; kk < 8; kk++) {
            float4 A0 = *(const float4*)(&sW[buf][kk][ty * 8]);
            float4 A1 = *(const float4*)(&sW[buf][kk][ty * 8 + 4]);
            float4 B0 = *(const float4*)(&sX[buf][kk][tx * 8]);
            float4 B1 = *(const float4*)(&sX[buf][kk][tx * 8 + 4]);
            float a[8]  = {A0.x, A0.y, A0.z, A0.w, A1.x, A1.y, A1.z, A1.w};
            float bv[8] = {B0.x, B0.y, B0.z, B0.w, B1.x, B1.y, B1.z, B1.w};
#pragma unroll
            for (int i = 0; i < 8; i++)
#pragma unroll
                for (int j = 0; j < 8; j++)
                    acc[i][j] = fmaf(a[i], bv[j], acc[i][j]);
        }

        if (has_next) {
            const int nb = buf ^ 1;
            sW[nb][0][tid] = w0n.x; sW[nb][1][tid] = w0n.y;
            sW[nb][2][tid] = w0n.z; sW[nb][3][tid] = w0n.w;
            sW[nb][4][tid] = w1n.x; sW[nb][5][tid] = w1n.y;
            sW[nb][6][tid] = w1n.z; sW[nb][7][tid] = w1n.w;
            *(float4*)(&sX[nb][xkk][xj4]) = xvn;
        }
        __syncthreads();
        buf ^= 1;
    }

    // Epilogue: BN + residual, write x_pw
#pragma unroll
    for (int i = 0; i < 8; i++) {
        const int o = o0 + ty * 8 + i;
        const float s  = gg[o] * rsqrtf(vv[o] + EPSV);
        const float sh = fmaf(-mm[o], s, bb[o]);
        const size_t base = ((size_t)bi * C_ + o) * HWSZ + hw0 + tx * 8;
        float4 xr0 = *(const float4*)(x + base);
        float4 xr1 = *(const float4*)(x + base + 4);
        float4 o0v, o1v;
        o0v.x = fmaf(acc[i][0], s, sh) + xr0.x;
        o0v.y = fmaf(acc[i][1], s, sh) + xr0.y;
        o0v.z = fmaf(acc[i][2], s, sh) + xr0.z;
        o0v.w = fmaf(acc[i][3], s, sh) + xr0.w;
        o1v.x = fmaf(acc[i][4], s, sh) + xr1.x;
        o1v.y = fmaf(acc[i][5], s, sh) + xr1.y;
        o1v.z = fmaf(acc[i][6], s, sh) + xr1.z;
        o1v.w = fmaf(acc[i][7], s, sh) + xr1.w;
        *(float4*)(g_xpw + base)     = o0v;
        *(float4*)(g_xpw + base + 4) = o1v;
    }
}

// ---------------------------------------------------------------------------
// Kernel 2: out = gelu( bn(dwconv13x13(x_pw)) + bn(x_pw * dw1_w) )
// One block per (band of 28 rows, channel, batch). 196 threads:
// tx in [0,7) -> 8-wide output strip, ty in [0,28) -> output row.
// 20-value register sliding window + vectorized weight rows.
// ---------------------------------------------------------------------------
__global__ void __launch_bounds__(196) dw_bn_gelu_kernel(
    const float* __restrict__ kw,
    const float* __restrict__ kg,  const float* __restrict__ kb,
    const float* __restrict__ km,  const float* __restrict__ kv,
    const float* __restrict__ d1w, const float* __restrict__ d1g,
    const float* __restrict__ d1b, const float* __restrict__ d1m,
    const float* __restrict__ d1v,
    float* __restrict__ out)
{
    __shared__ float s_in[40 * 72];   // 28+12 halo rows x (68 used, 72 padded)
    __shared__ float s_w[13 * 16];    // weight rows padded to 16 for float4 loads

    const int band = blockIdx.x;
    const int c    = blockIdx.y;
    const int bi   = blockIdx.z;
    const int tid  = threadIdx.x;
    const int r0   = band * 28;

    const float* src = g_xpw + ((size_t)bi * C_ + c) * HWSZ;

    // Load halo'd tile, zero-fill OOB (SAME padding)
    for (int idx = tid; idx < 40 * 68; idx += 196) {
        const int row = idx / 68;
        const int col = idx - row * 68;
        const int gh = r0 - 6 + row;
        const int gw = col - 6;
        float val = 0.f;
        if (gh >= 0 && gh < HH && gw >= 0 && gw < WW) val = src[gh * WW + gw];
        s_in[row * 72 + col] = val;
    }
    // Weights: padded rows of 16 (13 used). 208 slots > 196 threads -> strided loop!
    for (int idx = tid; idx < 13 * 16; idx += 196) {
        const int wr = idx >> 4;
        const int wc = idx & 15;
        s_w[idx] = (wc < 13) ? kw[(size_t)c * 169 + wr * 13 + wc] : 0.f;
    }
    __syncthreads();

    const int tx = tid % 7;
    const int ty = tid / 7;          // 0..27
    const int orow = r0 + ty;
    const int x8 = tx * 8;

    float acc[8];
#pragma unroll
    for (int q = 0; q < 8; q++) acc[q] = 0.f;

#pragma unroll
    for (int i = 0; i < 13; i++) {
        const float* rp = s_in + (ty + i) * 72 + x8;   // 16B aligned
        float r[20];
        *(float4*)&r[0]  = *(const float4*)(rp);
        *(float4*)&r[4]  = *(const float4*)(rp + 4);
        *(float4*)&r[8]  = *(const float4*)(rp + 8);
        *(float4*)&r[12] = *(const float4*)(rp + 12);
        *(float4*)&r[16] = *(const float4*)(rp + 16);
        float wv[16];
        const float* wp = s_w + i * 16;
        *(float4*)&wv[0]  = *(const float4*)(wp);
        *(float4*)&wv[4]  = *(const float4*)(wp + 4);
        *(float4*)&wv[8]  = *(const float4*)(wp + 8);
        *(float4*)&wv[12] = *(const float4*)(wp + 12);
#pragma unroll
        for (int j = 0; j < 13; j++) {
#pragma unroll
            for (int q = 0; q < 8; q++)
                acc[q] = fmaf(r[j + q], wv[j], acc[q]);
        }
    }

    // Per-channel constants
    const float sk  = kg[c] * rsqrtf(kv[c] + EPSV);
    const float shk = fmaf(-km[c], sk, kb[c]);
    const float s1  = d1g[c] * rsqrtf(d1v[c] + EPSV);
    const float a2  = d1w[c] * s1;
    const float b2  = fmaf(-d1m[c], s1, d1b[c]);

    // Center values for the 1x1-depthwise branch
    const float* cp = s_in + (ty + 6) * 72 + x8 + 6;

    const float RS2 = 0.70710678118654752f;
    float res[8];
#pragma unroll
    for (int q = 0; q < 8; q++) {
        const float v = fmaf(acc[q], sk, shk) + fmaf(cp[q], a2, b2);
        res[q] = 0.5f * v * (1.f + erff(v * RS2));
    }

    float* op = out + ((size_t)bi * C_ + c) * HWSZ + orow * WW + x8;
    *(float4*)(op)     = *(float4*)&res[0];
    *(float4*)(op + 4) = *(float4*)&res[4];
}

// ---------------------------------------------------------------------------
extern "C" void kernel_launch(void* const* d_in, const int* in_sizes, int n_in,
                              void* d_out, int out_size)
{
    const float* x     = (const float*)d_in[0];
    const float* pw_w  = (const float*)d_in[1];
    const float* pw_g  = (const float*)d_in[2];
    const float* pw_b  = (const float*)d_in[3];
    const float* pw_m  = (const float*)d_in[4];
    const float* pw_v  = (const float*)d_in[5];
    const float* dwk_w = (const float*)d_in[6];
    const float* dwk_g = (const float*)d_in[7];
    const float* dwk_b = (const float*)d_in[8];
    const float* dwk_m = (const float*)d_in[9];
    const float* dwk_v = (const float*)d_in[10];
    const float* dw1_w = (const float*)d_in[11];
    const float* dw1_g = (const float*)d_in[12];
    const float* dw1_b = (const float*)d_in[13];
    const float* dw1_m = (const float*)d_in[14];
    const float* dw1_v = (const float*)d_in[15];
    float* out = (float*)d_out;

    dim3 g1(HWSZ / 64, C_ / 128, NB);   // (49, 3, 16)
    pw_bn_res_kernel<<<g1, 128>>>(x, pw_w, pw_g, pw_b, pw_m, pw_v);

    dim3 g2(2, C_, NB);                 // bands of 28 rows
    dw_bn_gelu_kernel<<<g2, 196>>>(dwk_w, dwk_g, dwk_b, dwk_m, dwk_v,
                                   dw1_w, dw1_g, dw1_b, dw1_m, dw1_v, out);
}

// round 5
// speedup vs baseline: 1.7468x; 1.7468x over previous
#include <cuda_runtime.h>
#include <math.h>
#include <stdint.h>

#define C_    384
#define HH    56
#define WW    56
#define HWSZ  3136
#define NB    16
#define EPSV  1e-5f

// Scratch for x_pw: 16*384*3136 floats = 77 MB
__device__ float g_xpw[(size_t)NB * C_ * HWSZ];

__device__ __forceinline__ uint32_t cvt_tf32(float f) {
    uint32_t r;
    asm("cvt.rna.tf32.f32 %0, %1;" : "=r"(r) : "f"(f));
    return r;
}

#define MMA_TF32(c, a, b) \
    asm volatile("mma.sync.aligned.m16n8k8.row.col.f32.tf32.tf32.f32 " \
        "{%0,%1,%2,%3}, {%4,%5,%6,%7}, {%8,%9}, {%0,%1,%2,%3};" \
        : "+f"((c)[0]), "+f"((c)[1]), "+f"((c)[2]), "+f"((c)[3]) \
        : "r"((a)[0]), "r"((a)[1]), "r"((a)[2]), "r"((a)[3]), \
          "r"((b)[0]), "r"((b)[1]))

// ---------------------------------------------------------------------------
// Kernel 1: x_pw = bn(W @ x) + x, tensor-core tf32 mma.sync.
// CTA: M=128 (out channels), N=112 (hw), K=384, BK=16, double-buffered.
// 8 warps: warp_m = wid&3 (tile 32), warp_n = wid>>2 (tile 56).
// sA[k][m] stride 136, sB[k][n] stride 120: conflict-free fragment LDS.
// ---------------------------------------------------------------------------
__global__ void __launch_bounds__(256) gemm_pw_kernel(
    const float* __restrict__ x,  const float* __restrict__ w,
    const float* __restrict__ gg, const float* __restrict__ bb,
    const float* __restrict__ mm, const float* __restrict__ vv)
{
    __shared__ uint32_t sA[2][16][136];   // [buf][k][m] (128 used)
    __shared__ uint32_t sB[2][16][120];   // [buf][k][n] (112 used)

    const int tid = threadIdx.x;
    const int wid = tid >> 5;
    const int lane = tid & 31;
    const int g   = lane >> 2;       // groupID 0..7
    const int tig = lane & 3;        // thread-in-group 0..3
    const int wm  = (wid & 3) * 32;  // warp M offset
    const int wn  = (wid >> 2) * 56; // warp N offset

    const int bi = blockIdx.z;
    const int m0 = blockIdx.y * 128;
    const int p0 = blockIdx.x * 112;

    const float* xb = x + (size_t)bi * C_ * HWSZ;

    float acc[2][7][4];
#pragma unroll
    for (int mt = 0; mt < 2; mt++)
#pragma unroll
        for (int nt = 0; nt < 7; nt++)
#pragma unroll
            for (int q = 0; q < 4; q++) acc[mt][nt][q] = 0.f;

    // ---- staging index precompute ----
    // A: 512 float4 per stage: q -> m = q>>2, kq = q&3 (cols kq*4..+3)
    const int aq0 = tid, aq1 = tid + 256;
    const int am0 = aq0 >> 2, akq0 = aq0 & 3;
    const int am1 = aq1 >> 2, akq1 = aq1 & 3;
    const float* wp0 = w + (size_t)(m0 + am0) * C_ + akq0 * 4;
    const float* wp1 = w + (size_t)(m0 + am1) * C_ + akq1 * 4;
    // B: 448 float4 per stage: q -> kr = q/28, nq = q%28
    const int bq0 = tid, bq1 = tid + 256;
    const int bkr0 = bq0 / 28, bnq0 = bq0 - bkr0 * 28;
    const int bkr1 = bq1 / 28, bnq1 = bq1 - bkr1 * 28;
    const bool bv1 = bq1 < 448;
    const float* xp0 = xb + (size_t)bkr0 * HWSZ + p0 + bnq0 * 4;
    const float* xp1 = bv1 ? (xb + (size_t)bkr1 * HWSZ + p0 + bnq1 * 4) : xp0;

    // ---- stage 0 ----
    {
        float4 a0 = *(const float4*)(wp0);
        float4 a1 = *(const float4*)(wp1);
        sA[0][akq0 * 4 + 0][am0] = cvt_tf32(a0.x);
        sA[0][akq0 * 4 + 1][am0] = cvt_tf32(a0.y);
        sA[0][akq0 * 4 + 2][am0] = cvt_tf32(a0.z);
        sA[0][akq0 * 4 + 3][am0] = cvt_tf32(a0.w);
        sA[0][akq1 * 4 + 0][am1] = cvt_tf32(a1.x);
        sA[0][akq1 * 4 + 1][am1] = cvt_tf32(a1.y);
        sA[0][akq1 * 4 + 2][am1] = cvt_tf32(a1.z);
        sA[0][akq1 * 4 + 3][am1] = cvt_tf32(a1.w);
        float4 b0 = *(const float4*)(xp0);
        uint4 t0 = {cvt_tf32(b0.x), cvt_tf32(b0.y), cvt_tf32(b0.z), cvt_tf32(b0.w)};
        *(uint4*)(&sB[0][bkr0][bnq0 * 4]) = t0;
        if (bv1) {
            float4 b1 = *(const float4*)(xp1);
            uint4 t1 = {cvt_tf32(b1.x), cvt_tf32(b1.y), cvt_tf32(b1.z), cvt_tf32(b1.w)};
            *(uint4*)(&sB[0][bkr1][bnq1 * 4]) = t1;
        }
    }
    __syncthreads();

    for (int kc = 0; kc < 24; kc++) {
        const int buf = kc & 1;
        const bool more = kc < 23;
        float4 pa0, pa1, pb0, pb1;
        if (more) {
            const int kn = (kc + 1) * 16;
            pa0 = *(const float4*)(wp0 + kn);
            pa1 = *(const float4*)(wp1 + kn);
            pb0 = *(const float4*)(xp0 + (size_t)kn * HWSZ);
            if (bv1) pb1 = *(const float4*)(xp1 + (size_t)kn * HWSZ);
        }

#pragma unroll
        for (int kk = 0; kk < 2; kk++) {
            const int kr = kk * 8 + tig;
            const uint32_t* A0 = &sA[buf][kr][wm];
            const uint32_t* A4 = &sA[buf][kr + 4][wm];
            const uint32_t* B0 = &sB[buf][kr][wn];
            const uint32_t* B4 = &sB[buf][kr + 4][wn];
            uint32_t a[2][4], b[7][2];
#pragma unroll
            for (int mt = 0; mt < 2; mt++) {
                a[mt][0] = A0[mt * 16 + g];
                a[mt][1] = A0[mt * 16 + g + 8];
                a[mt][2] = A4[mt * 16 + g];
                a[mt][3] = A4[mt * 16 + g + 8];
            }
#pragma unroll
            for (int nt = 0; nt < 7; nt++) {
                b[nt][0] = B0[nt * 8 + g];
                b[nt][1] = B4[nt * 8 + g];
            }
#pragma unroll
            for (int mt = 0; mt < 2; mt++)
#pragma unroll
                for (int nt = 0; nt < 7; nt++)
                    MMA_TF32(acc[mt][nt], a[mt], b[nt]);
        }

        if (more) {
            const int nb = buf ^ 1;
            sA[nb][akq0 * 4 + 0][am0] = cvt_tf32(pa0.x);
            sA[nb][akq0 * 4 + 1][am0] = cvt_tf32(pa0.y);
            sA[nb][akq0 * 4 + 2][am0] = cvt_tf32(pa0.z);
            sA[nb][akq0 * 4 + 3][am0] = cvt_tf32(pa0.w);
            sA[nb][akq1 * 4 + 0][am1] = cvt_tf32(pa1.x);
            sA[nb][akq1 * 4 + 1][am1] = cvt_tf32(pa1.y);
            sA[nb][akq1 * 4 + 2][am1] = cvt_tf32(pa1.z);
            sA[nb][akq1 * 4 + 3][am1] = cvt_tf32(pa1.w);
            uint4 t0 = {cvt_tf32(pb0.x), cvt_tf32(pb0.y), cvt_tf32(pb0.z), cvt_tf32(pb0.w)};
            *(uint4*)(&sB[nb][bkr0][bnq0 * 4]) = t0;
            if (bv1) {
                uint4 t1 = {cvt_tf32(pb1.x), cvt_tf32(pb1.y), cvt_tf32(pb1.z), cvt_tf32(pb1.w)};
                *(uint4*)(&sB[nb][bkr1][bnq1 * 4]) = t1;
            }
        }
        __syncthreads();
    }

    // ---- epilogue: BN + residual -> g_xpw ----
    // Thread owns rows o = m0+wm+mt*16+g(+8), cols hw = p0+wn+nt*8+2*tig(+1)
    float sc[2][2], sh[2][2];
#pragma unroll
    for (int mt = 0; mt < 2; mt++)
#pragma unroll
        for (int h = 0; h < 2; h++) {
            const int o = m0 + wm + mt * 16 + h * 8 + g;
            const float s = gg[o] * rsqrtf(vv[o] + EPSV);
            sc[mt][h] = s;
            sh[mt][h] = fmaf(-mm[o], s, bb[o]);
        }

#pragma unroll
    for (int mt = 0; mt < 2; mt++)
#pragma unroll
        for (int h = 0; h < 2; h++) {
            const int o = m0 + wm + mt * 16 + h * 8 + g;
            const size_t rb = ((size_t)bi * C_ + o) * HWSZ + p0 + wn + 2 * tig;
#pragma unroll
            for (int nt = 0; nt < 7; nt++) {
                const size_t idx = rb + nt * 8;
                float2 xr = *(const float2*)(x + idx);
                const float c0 = acc[mt][nt][h * 2 + 0];
                const float c1 = acc[mt][nt][h * 2 + 1];
                float2 ov;
                ov.x = fmaf(c0, sc[mt][h], sh[mt][h]) + xr.x;
                ov.y = fmaf(c1, sc[mt][h], sh[mt][h]) + xr.y;
                *(float2*)(g_xpw + idx) = ov;
            }
        }
}

// ---------------------------------------------------------------------------
// Kernel 2 (round-1 proven): out = gelu(bn(dwconv13(x_pw)) + bn(x_pw*dw1_w))
// ---------------------------------------------------------------------------
__global__ void __launch_bounds__(224) dw_bn_gelu_kernel(
    const float* __restrict__ kw,
    const float* __restrict__ kg,  const float* __restrict__ kb,
    const float* __restrict__ km,  const float* __restrict__ kv,
    const float* __restrict__ d1w, const float* __restrict__ d1g,
    const float* __restrict__ d1b, const float* __restrict__ d1m,
    const float* __restrict__ d1v,
    float* __restrict__ out)
{
    __shared__ float s_in[28 * 72];
    __shared__ float s_w[169];

    const int band = blockIdx.x;
    const int c    = blockIdx.y;
    const int bi   = blockIdx.z;
    const int tid  = threadIdx.x;
    const int r0   = band * 16;

    const float* src = g_xpw + ((size_t)bi * C_ + c) * HWSZ;

    for (int idx = tid; idx < 28 * 68; idx += 224) {
        const int row = idx / 68;
        const int col = idx - row * 68;
        const int gh = r0 - 6 + row;
        const int gw = col - 6;
        float val = 0.f;
        if (gh >= 0 && gh < HH && gw >= 0 && gw < WW) val = src[gh * WW + gw];
        s_in[row * 72 + col] = val;
    }
    if (tid < 169) s_w[tid] = kw[(size_t)c * 169 + tid];
    __syncthreads();

    const int tx = tid % 14;
    const int ty = tid / 14;
    const int orow = r0 + ty;
    if (orow >= HH) return;

    const int x4 = tx * 4;
    float acc0 = 0.f, acc1 = 0.f, acc2 = 0.f, acc3 = 0.f;

#pragma unroll
    for (int i = 0; i < 13; i++) {
        const float* rp = s_in + (ty + i) * 72 + x4;
        float r[16];
        *(float4*)&r[0]  = *(const float4*)(rp);
        *(float4*)&r[4]  = *(const float4*)(rp + 4);
        *(float4*)&r[8]  = *(const float4*)(rp + 8);
        *(float4*)&r[12] = *(const float4*)(rp + 12);
#pragma unroll
        for (int j = 0; j < 13; j++) {
            const float wv = s_w[i * 13 + j];
            acc0 = fmaf(r[j + 0], wv, acc0);
            acc1 = fmaf(r[j + 1], wv, acc1);
            acc2 = fmaf(r[j + 2], wv, acc2);
            acc3 = fmaf(r[j + 3], wv, acc3);
        }
    }

    const float sk  = kg[c] * rsqrtf(kv[c] + EPSV);
    const float shk = fmaf(-km[c], sk, kb[c]);
    const float s1  = d1g[c] * rsqrtf(d1v[c] + EPSV);
    const float a2  = d1w[c] * s1;
    const float b2  = fmaf(-d1m[c], s1, d1b[c]);

    const float* cp = s_in + (ty + 6) * 72 + x4 + 6;
    const float v0 = fmaf(acc0, sk, shk) + fmaf(cp[0], a2, b2);
    const float v1 = fmaf(acc1, sk, shk) + fmaf(cp[1], a2, b2);
    const float v2 = fmaf(acc2, sk, shk) + fmaf(cp[2], a2, b2);
    const float v3 = fmaf(acc3, sk, shk) + fmaf(cp[3], a2, b2);

    const float RS2 = 0.70710678118654752f;
    float4 res;
    res.x = 0.5f * v0 * (1.f + erff(v0 * RS2));
    res.y = 0.5f * v1 * (1.f + erff(v1 * RS2));
    res.z = 0.5f * v2 * (1.f + erff(v2 * RS2));
    res.w = 0.5f * v3 * (1.f + erff(v3 * RS2));

    *(float4*)(out + ((size_t)bi * C_ + c) * HWSZ + orow * WW + x4) = res;
}

// ---------------------------------------------------------------------------
extern "C" void kernel_launch(void* const* d_in, const int* in_sizes, int n_in,
                              void* d_out, int out_size)
{
    const float* x     = (const float*)d_in[0];
    const float* pw_w  = (const float*)d_in[1];
    const float* pw_g  = (const float*)d_in[2];
    const float* pw_b  = (const float*)d_in[3];
    const float* pw_m  = (const float*)d_in[4];
    const float* pw_v  = (const float*)d_in[5];
    const float* dwk_w = (const float*)d_in[6];
    const float* dwk_g = (const float*)d_in[7];
    const float* dwk_b = (const float*)d_in[8];
    const float* dwk_m = (const float*)d_in[9];
    const float* dwk_v = (const float*)d_in[10];
    const float* dw1_w = (const float*)d_in[11];
    const float* dw1_g = (const float*)d_in[12];
    const float* dw1_b = (const float*)d_in[13];
    const float* dw1_m = (const float*)d_in[14];
    const float* dw1_v = (const float*)d_in[15];
    float* out = (float*)d_out;

    dim3 g1(HWSZ / 112, C_ / 128, NB);   // (28, 3, 16)
    gemm_pw_kernel<<<g1, 256>>>(x, pw_w, pw_g, pw_b, pw_m, pw_v);

    dim3 g2((HH + 15) / 16, C_, NB);     // (4, 384, 16)
    dw_bn_gelu_kernel<<<g2, 224>>>(dwk_w, dwk_g, dwk_b, dwk_m, dwk_v,
                                   dw1_w, dw1_g, dw1_b, dw1_m, dw1_v, out);
}